// round 2
// baseline (speedup 1.0000x reference)
#include <cuda_runtime.h>
#include <cstdint>

// ---------------- problem constants ----------------
#define BATCH   32
#define NTOK    1024
#define DDIM    1024
#define MFF     4096
#define LN_EPS  1e-5f
#define GN      64
#define GKC     32

#define MS_SPLIT 8
#define F1_SPLIT 4
#define F2_SPLIT 16

// ---------------- scratch (no allocation allowed) ----------------
__device__ float g_x   [BATCH * NTOK];        // A + Q (attention output + residual)
__device__ float g_part[1048576];             // split-K partial sums (4 MB)

#define MU_OFF   0                            // 8*32*1024 = 262144
#define SIG_OFF  262144                       // 8*32*1024 = 262144
#define W1_OFF   0                            // 4*32*4096 = 524288 (reused after gauss)
#define W2_OFF   524288                       // 16*32*1024 = 524288

// =====================================================================
// Fused split-K GEMM.
//   amode 0: A = LN(Q)   (stats + gamma/beta computed inline from Q)
//   amode 1: A = LN(g_x) (stats + gamma/beta computed inline from g_x)
//   amode 2: A = silu(sum of FFN1 partials + b1)  (computed inline)
// C_part[split][m][n] = A[m, kOff:kOff+kps] . W[n, kOff:kOff+kps]
// Tile 32(M) x 64(N), K-chunk 32, double-buffered smem, W duplicated in
// smem as {w,w} pairs so the inner loop is pure LDS.64 + fma.f32x2.
// gridDim = (N/64, nsplit, nz); z selects W0/W1 (mu/sigma fusion).
// =====================================================================
__global__ __launch_bounds__(256, 2)
void gemm_kernel(const float* __restrict__ W0, const float* __restrict__ W1,
                 int ldw, int N, int kPerSplit, int partOff, int partStrideZ,
                 int amode,
                 const float* __restrict__ Ain,     // amode 0: Q
                 const float* __restrict__ lng,
                 const float* __restrict__ lnb,
                 const float* __restrict__ b1)
{
    const float* __restrict__ A = (amode == 1) ? g_x : Ain;

    __shared__ __align__(16) float a_s[2][GKC][34];
    __shared__ __align__(16) float w_s[2][GKC][130];
    __shared__ float sh_mean[32], sh_rs[32];

    const int tid = threadIdx.x;

    // ---- inline LayerNorm stats (redundant per block; L2-resident) ----
    if (amode < 2) {
        const int r = tid >> 3;          // row 0..31
        const int c = tid & 7;           // 8 threads per row
        const float4* p = reinterpret_cast<const float4*>(A + r * NTOK + c * 128);
        float s = 0.f, ss = 0.f;
        #pragma unroll 8
        for (int i = 0; i < 32; ++i) {
            float4 v = p[i];
            s  += v.x + v.y + v.z + v.w;
            ss += v.x*v.x + v.y*v.y + v.z*v.z + v.w*v.w;
        }
        #pragma unroll
        for (int o = 4; o; o >>= 1) {
            s  += __shfl_xor_sync(0xffffffffu, s,  o);
            ss += __shfl_xor_sync(0xffffffffu, ss, o);
        }
        if (c == 0) {
            const float mean = s * (1.0f / NTOK);
            const float var  = ss * (1.0f / NTOK) - mean * mean;
            sh_mean[r] = mean;
            sh_rs[r]   = rsqrtf(var + LN_EPS);
        }
        __syncthreads();
    }

    const float* __restrict__ W = (blockIdx.z == 0) ? W0 : W1;
    float* __restrict__ P = g_part + partOff + (size_t)blockIdx.z * partStrideZ;

    const int j0    = blockIdx.x * GN;
    const int split = blockIdx.y;
    const int kOff  = split * kPerSplit;

    const int tx = tid & 31;          // n within tile
    const int ty = tid >> 5;          // m-pair group (0..7)
    const int ra = tid >> 3;          // load row 0..31
    const int ca = tid & 7;           // load col-group 0..7
    const int c4 = ca * 4;

    const float* Wr0 = W + (size_t)(j0 + ra)      * ldw + kOff + c4;
    const float* Wr1 = W + (size_t)(j0 + ra + 32) * ldw + kOff + c4;

    const int T = kPerSplit / GKC;

    float4 fw0, fw1;
    float4 fa, fg, fb;                 // amode < 2
    float4 p0, p1, p2, p3, pb;         // amode == 2

    auto loadRegs = [&](int t) {
        fw0 = *reinterpret_cast<const float4*>(Wr0 + t * GKC);
        fw1 = *reinterpret_cast<const float4*>(Wr1 + t * GKC);
        const int kc = kOff + t * GKC + c4;
        if (amode < 2) {
            fa = *reinterpret_cast<const float4*>(A   + ra * NTOK + kc);
            fg = *reinterpret_cast<const float4*>(lng + kc);
            fb = *reinterpret_cast<const float4*>(lnb + kc);
        } else {
            const float* base = g_part + W1_OFF + (size_t)ra * MFF + kc;
            p0 = *reinterpret_cast<const float4*>(base);
            p1 = *reinterpret_cast<const float4*>(base + 1 * BATCH * MFF);
            p2 = *reinterpret_cast<const float4*>(base + 2 * BATCH * MFF);
            p3 = *reinterpret_cast<const float4*>(base + 3 * BATCH * MFF);
            pb = *reinterpret_cast<const float4*>(b1 + kc);
        }
    };

    auto storeRegs = [&](int buf) {
        float av[4];
        if (amode < 2) {
            const float mean = sh_mean[ra];
            const float rs   = sh_rs[ra];
            av[0] = (fa.x - mean) * rs * fg.x + fb.x;
            av[1] = (fa.y - mean) * rs * fg.y + fb.y;
            av[2] = (fa.z - mean) * rs * fg.z + fb.z;
            av[3] = (fa.w - mean) * rs * fg.w + fb.w;
        } else {
            float v;
            v = pb.x + p0.x + p1.x + p2.x + p3.x;  av[0] = v / (1.0f + __expf(-v));
            v = pb.y + p0.y + p1.y + p2.y + p3.y;  av[1] = v / (1.0f + __expf(-v));
            v = pb.z + p0.z + p1.z + p2.z + p3.z;  av[2] = v / (1.0f + __expf(-v));
            v = pb.w + p0.w + p1.w + p2.w + p3.w;  av[3] = v / (1.0f + __expf(-v));
        }
        #pragma unroll
        for (int j = 0; j < 4; ++j) a_s[buf][c4 + j][ra] = av[j];

        // W duplicated: w_s[kk][2n] = w_s[kk][2n+1] = W[n][kk]
        *reinterpret_cast<float2*>(&w_s[buf][c4 + 0][2 * ra])      = make_float2(fw0.x, fw0.x);
        *reinterpret_cast<float2*>(&w_s[buf][c4 + 1][2 * ra])      = make_float2(fw0.y, fw0.y);
        *reinterpret_cast<float2*>(&w_s[buf][c4 + 2][2 * ra])      = make_float2(fw0.z, fw0.z);
        *reinterpret_cast<float2*>(&w_s[buf][c4 + 3][2 * ra])      = make_float2(fw0.w, fw0.w);
        *reinterpret_cast<float2*>(&w_s[buf][c4 + 0][2 * ra + 64]) = make_float2(fw1.x, fw1.x);
        *reinterpret_cast<float2*>(&w_s[buf][c4 + 1][2 * ra + 64]) = make_float2(fw1.y, fw1.y);
        *reinterpret_cast<float2*>(&w_s[buf][c4 + 2][2 * ra + 64]) = make_float2(fw1.z, fw1.z);
        *reinterpret_cast<float2*>(&w_s[buf][c4 + 3][2 * ra + 64]) = make_float2(fw1.w, fw1.w);
    };

    loadRegs(0);
    storeRegs(0);
    __syncthreads();

    unsigned long long acc00 = 0ull, acc01 = 0ull, acc10 = 0ull, acc11 = 0ull;

    for (int t = 0; t < T; ++t) {
        const int cur = t & 1;
        if (t + 1 < T) loadRegs(t + 1);
        #pragma unroll
        for (int kk = 0; kk < GKC; ++kk) {
            unsigned long long a0 = *reinterpret_cast<const unsigned long long*>(&a_s[cur][kk][2*ty]);
            unsigned long long a1 = *reinterpret_cast<const unsigned long long*>(&a_s[cur][kk][2*ty + 16]);
            unsigned long long w0 = *reinterpret_cast<const unsigned long long*>(&w_s[cur][kk][2*tx]);
            unsigned long long w1 = *reinterpret_cast<const unsigned long long*>(&w_s[cur][kk][2*tx + 64]);
            asm("fma.rn.f32x2 %0, %1, %2, %0;" : "+l"(acc00) : "l"(a0), "l"(w0));
            asm("fma.rn.f32x2 %0, %1, %2, %0;" : "+l"(acc01) : "l"(a0), "l"(w1));
            asm("fma.rn.f32x2 %0, %1, %2, %0;" : "+l"(acc10) : "l"(a1), "l"(w0));
            asm("fma.rn.f32x2 %0, %1, %2, %0;" : "+l"(acc11) : "l"(a1), "l"(w1));
        }
        if (t + 1 < T) {
            storeRegs((t + 1) & 1);
            __syncthreads();
        }
    }

    // write partials: m in {2ty,2ty+1,2ty+16,2ty+17}, n in {j0+tx, j0+tx+32}
    float l, h;
    const int m0 = 2 * ty, m1 = 2 * ty + 16;
    const int n0 = j0 + tx, n1 = j0 + tx + 32;
    const size_t base = (size_t)(split * BATCH) * N;
    asm("mov.b64 {%0, %1}, %2;" : "=f"(l), "=f"(h) : "l"(acc00));
    P[base + (size_t)m0 * N + n0] = l;  P[base + (size_t)(m0+1) * N + n0] = h;
    asm("mov.b64 {%0, %1}, %2;" : "=f"(l), "=f"(h) : "l"(acc01));
    P[base + (size_t)m0 * N + n1] = l;  P[base + (size_t)(m0+1) * N + n1] = h;
    asm("mov.b64 {%0, %1}, %2;" : "=f"(l), "=f"(h) : "l"(acc10));
    P[base + (size_t)m1 * N + n0] = l;  P[base + (size_t)(m1+1) * N + n0] = h;
    asm("mov.b64 {%0, %1}, %2;" : "=f"(l), "=f"(h) : "l"(acc11));
    P[base + (size_t)m1 * N + n1] = l;  P[base + (size_t)(m1+1) * N + n1] = h;
}

// =====================================================================
// Gaussian pseudo-attention: one warp per (b,i) row, streams K/V (256 MB)
// with evict-first loads. Folds the mu/sigma split-K combine per row.
// g_x[b,i] = Q[b,i] + sum_d exp(coef*(K-mu)^2) * V
// =====================================================================
__global__ __launch_bounds__(256)
void gauss_kernel(const float* __restrict__ Kp,
                  const float* __restrict__ Vp,
                  const float* __restrict__ Qp,
                  const float* __restrict__ mu_b,
                  const float* __restrict__ sig_b)
{
    const int w    = (blockIdx.x * blockDim.x + threadIdx.x) >> 5;
    const int lane = threadIdx.x & 31;
    const int b = w >> 10;
    const int i = w & 1023;

    float mu = mu_b[i];
    float sg = sig_b[i];
    #pragma unroll
    for (int s = 0; s < MS_SPLIT; ++s) {
        mu += g_part[MU_OFF  + (s * BATCH + b) * NTOK + i];
        sg += g_part[SIG_OFF + (s * BATCH + b) * NTOK + i];
    }
    mu = tanhf(mu);
    const float coef = -0.5f / (sg * sg + 1e-8f);

    const float4* K4 = reinterpret_cast<const float4*>(Kp) + (size_t)w * (DDIM / 4);
    const float4* V4 = reinterpret_cast<const float4*>(Vp) + (size_t)w * (DDIM / 4);

    float acc = 0.f;
    #pragma unroll
    for (int it = 0; it < 8; ++it) {
        const float4 k4 = __ldcs(&K4[it * 32 + lane]);
        const float4 v4 = __ldcs(&V4[it * 32 + lane]);
        float d;
        d = k4.x - mu; acc += __expf(coef * d * d) * v4.x;
        d = k4.y - mu; acc += __expf(coef * d * d) * v4.y;
        d = k4.z - mu; acc += __expf(coef * d * d) * v4.z;
        d = k4.w - mu; acc += __expf(coef * d * d) * v4.w;
    }
    #pragma unroll
    for (int o = 16; o; o >>= 1) acc += __shfl_xor_sync(0xffffffffu, acc, o);
    if (lane == 0) g_x[w] = acc + Qp[w];
}

// =====================================================================
// final combine: out = x + b2 + sum_16 w2_parts            (32 x 1024)
// =====================================================================
__global__ void final_kernel(const float* __restrict__ b2,
                             float* __restrict__ out)
{
    const int t  = blockIdx.x * blockDim.x + threadIdx.x;   // 0..8191 (float4)
    const int m  = t >> 8;
    const int j4 = t & 255;
    float4 s = reinterpret_cast<const float4*>(g_x)[t];
    const float4 bb = reinterpret_cast<const float4*>(b2)[j4];
    s.x += bb.x; s.y += bb.y; s.z += bb.z; s.w += bb.w;
    #pragma unroll
    for (int sp = 0; sp < F2_SPLIT; ++sp) {
        const float4 p = *reinterpret_cast<const float4*>(
            g_part + W2_OFF + (size_t)(sp * BATCH + m) * NTOK + j4 * 4);
        s.x += p.x; s.y += p.y; s.z += p.z; s.w += p.w;
    }
    reinterpret_cast<float4*>(out)[t] = s;
}

// =====================================================================
extern "C" void kernel_launch(void* const* d_in, const int* in_sizes, int n_in,
                              void* d_out, int out_size)
{
    const float* Q       = (const float*)d_in[0];
    const float* Kt      = (const float*)d_in[1];
    const float* Vt      = (const float*)d_in[2];
    const float* mu_w    = (const float*)d_in[3];
    const float* mu_b    = (const float*)d_in[4];
    const float* sigma_w = (const float*)d_in[5];
    const float* sigma_b = (const float*)d_in[6];
    const float* ffn_w1  = (const float*)d_in[7];
    const float* ffn_b1  = (const float*)d_in[8];
    const float* ffn_w2  = (const float*)d_in[9];
    const float* ffn_b2  = (const float*)d_in[10];
    const float* ln_ff_g = (const float*)d_in[11];
    const float* ln_ff_b = (const float*)d_in[12];
    const float* ln_q_g  = (const float*)d_in[13];
    const float* ln_q_b  = (const float*)d_in[14];
    float* out = (float*)d_out;

    // 1. mu & sigma partial GEMMs on LN(Q) (inline LN), split-K 8, z: mu/sigma
    gemm_kernel<<<dim3(NTOK / GN, MS_SPLIT, 2), 256>>>(
        mu_w, sigma_w, NTOK, NTOK, NTOK / MS_SPLIT,
        MU_OFF, SIG_OFF - MU_OFF, 0, Q, ln_q_g, ln_q_b, nullptr);

    // 2. Gaussian stream (dominant) + mu/sigma combine fold, writes g_x
    gauss_kernel<<<(BATCH * NTOK * 32) / 256, 256>>>(Kt, Vt, Q, mu_b, sigma_b);

    // 3. FFN GEMM 1 on LN(g_x) (inline LN), split-K 4
    gemm_kernel<<<dim3(MFF / GN, F1_SPLIT, 1), 256>>>(
        ffn_w1, ffn_w1, NTOK, MFF, NTOK / F1_SPLIT,
        W1_OFF, 0, 1, nullptr, ln_ff_g, ln_ff_b, nullptr);

    // 4. FFN GEMM 2 on silu(FFN1 partials + b1) (inline silu), split-K 16
    gemm_kernel<<<dim3(NTOK / GN, F2_SPLIT, 1), 256>>>(
        ffn_w2, ffn_w2, MFF, NTOK, MFF / F2_SPLIT,
        W2_OFF, 0, 2, nullptr, nullptr, nullptr, ffn_b1);

    // 5. out = x + b2 + sum of FFN2 partials
    final_kernel<<<BATCH, 256>>>(ffn_b2, out);
}